// round 3
// baseline (speedup 1.0000x reference)
#include <cuda_runtime.h>

#define U_LEN 4096
#define B_SZ  64
#define H_DIM 64
#define T_TOT (U_LEN * B_SZ)   // 262144 sequential steps

// ---------------------------------------------------------------------------
// Packed f32x2 helpers (Blackwell sm_103a)
// ---------------------------------------------------------------------------
__device__ __forceinline__ unsigned long long ffma2(unsigned long long a,
                                                    unsigned long long b,
                                                    unsigned long long c) {
    unsigned long long d;
    asm("fma.rn.f32x2 %0, %1, %2, %3;" : "=l"(d) : "l"(a), "l"(b), "l"(c));
    return d;
}
__device__ __forceinline__ unsigned long long fadd2(unsigned long long a,
                                                    unsigned long long b) {
    unsigned long long d;
    asm("add.rn.f32x2 %0, %1, %2;" : "=l"(d) : "l"(a), "l"(b));
    return d;
}

// ---------------------------------------------------------------------------
// Kernel 1: x[t][j] = sum_k emb[ids[t]][k] * W_ih[j][k] + (b_ih[j] + b_hh[j])
// ids[t] = y[t % B, t / B]   (time-major flatten of y.T)
// Writes x directly into d_out; the scan kernel consumes it in place.
// ---------------------------------------------------------------------------
#define TOK_PER_BLOCK 64

__global__ void xproj_kernel(const int* __restrict__ y,
                             const float* __restrict__ emb,
                             const float* __restrict__ Wih,
                             const float* __restrict__ bih,
                             const float* __restrict__ bhh,
                             float* __restrict__ xo) {
    __shared__ float Wt[H_DIM][H_DIM];   // Wt[k][j] = Wih[j][k] (conflict-free reads)
    __shared__ float bias[H_DIM];
    __shared__ float e[4][H_DIM];

    const int tid = threadIdx.x;          // 256 threads
    for (int i = tid; i < H_DIM * H_DIM; i += 256) {
        int jj = i >> 6, kk = i & 63;
        Wt[kk][jj] = Wih[i];
    }
    if (tid < H_DIM) bias[tid] = bih[tid] + bhh[tid];
    __syncthreads();

    const int s = tid >> 6;               // token slot 0..3
    const int j = tid & 63;               // output feature
    const long base = (long)blockIdx.x * TOK_PER_BLOCK;

    for (int it = 0; it < TOK_PER_BLOCK; it += 4) {
        long t = base + it + s;
        int b = (int)(t & 63);            // t % B
        int i = (int)(t >> 6);            // t / B
        int id = y[b * U_LEN + i];
        e[s][j] = emb[(long)id * H_DIM + j];
        __syncthreads();

        float acc = bias[j];
#pragma unroll
        for (int k = 0; k < H_DIM; k++)
            acc = fmaf(e[s][k], Wt[k][j], acc);
        xo[t * H_DIM + j] = acc;
        __syncthreads();                  // protect e[] WAR for next iteration
    }
}

// ---------------------------------------------------------------------------
// Kernel 2: the sequential recurrence  h <- tanh(x_t + W_hh h),  T_TOT steps.
// Single block, 64 threads (2 warps). Thread j owns output j:
//   - W_hh row j lives in registers as 32 packed f32x2 pairs
//   - h broadcast through double-buffered smem (one bar.sync per step)
//   - x read from d_out 8 steps ahead (register ring), h written behind.
//     Thread j only touches global column j -> no cross-thread hazards.
// ---------------------------------------------------------------------------
__global__ void __launch_bounds__(64, 1)
scan_kernel(const float* __restrict__ Whh,
            const float* __restrict__ h0,
            float* __restrict__ xo) {
    const int j = threadIdx.x;            // 0..63

    // Load W_hh[j][0..63] as packed pairs (row is 256B aligned).
    unsigned long long w[32];
    const double2* wrow = reinterpret_cast<const double2*>(Whh + j * H_DIM);
#pragma unroll
    for (int m = 0; m < 16; m++) {
        double2 d = wrow[m];
        w[2 * m]     = __double_as_longlong(d.x);
        w[2 * m + 1] = __double_as_longlong(d.y);
    }

    __shared__ __align__(16) float hs[2][H_DIM];
    hs[0][j] = h0[j];
    __syncthreads();

    const int PF = 8;                     // prefetch distance (covers DRAM latency)
    float xr[PF];
#pragma unroll
    for (int u = 0; u < PF; u++) xr[u] = xo[u * H_DIM + j];

    for (int base = 0; base < T_TOT; base += PF) {
#pragma unroll
        for (int u = 0; u < PF; u++) {
            const int t = base + u;
            const double2* hp = reinterpret_cast<const double2*>(hs[t & 1]);

            unsigned long long a0 = 0ull, a1 = 0ull, a2 = 0ull, a3 = 0ull;
#pragma unroll
            for (int m = 0; m < 8; m++) {          // 4 chains x 8 deep, LDS.128 loads
                double2 d0 = hp[2 * m];
                double2 d1 = hp[2 * m + 1];
                a0 = ffma2(w[4 * m + 0], __double_as_longlong(d0.x), a0);
                a1 = ffma2(w[4 * m + 1], __double_as_longlong(d0.y), a1);
                a2 = ffma2(w[4 * m + 2], __double_as_longlong(d1.x), a2);
                a3 = ffma2(w[4 * m + 3], __double_as_longlong(d1.y), a3);
            }
            a0 = fadd2(a0, a1);
            a2 = fadd2(a2, a3);
            a0 = fadd2(a0, a2);
            float lo = __int_as_float((unsigned)(a0 & 0xffffffffull));
            float hi = __int_as_float((unsigned)(a0 >> 32));
            float v  = lo + hi + xr[u];
            float h  = tanhf(v);

            xo[(long)t * H_DIM + j] = h;           // overwrite x_t with h_t
            hs[(t + 1) & 1][j] = h;

            int tn = t + PF;                       // prefetch next x (always ahead
            if (tn < T_TOT)                        //  of the write frontier)
                xr[u] = xo[(long)tn * H_DIM + j];

            __syncthreads();
        }
    }
}

// ---------------------------------------------------------------------------
extern "C" void kernel_launch(void* const* d_in, const int* in_sizes, int n_in,
                              void* d_out, int out_size) {
    const int*   y    = (const int*)d_in[0];
    const float* emb  = (const float*)d_in[1];
    const float* Wih  = (const float*)d_in[2];
    const float* Whh  = (const float*)d_in[3];
    const float* bih  = (const float*)d_in[4];
    const float* bhh  = (const float*)d_in[5];
    const float* h0   = (const float*)d_in[6];
    float* out = (float*)d_out;

    xproj_kernel<<<T_TOT / TOK_PER_BLOCK, 256>>>(y, emb, Wih, bih, bhh, out);
    scan_kernel<<<1, 64>>>(Whh, h0, out);
}